// round 15
// baseline (speedup 1.0000x reference)
#include <cuda_runtime.h>
#include <cuda_fp16.h>
#include <cstdint>
#include <math.h>

#define B_   16
#define N_   1024
#define P_   8
#define H_   300
#define HP_  320
#define MT   128
#define KB   64      // int8 k-elems per chunk (2 mma k-steps)
#define NKT  5       // 320/64

#define QMAXF 16256.0f   // 127*128

// ---------------- device-global scratch ----------------
__device__ __align__(16) int8_t g_Wq[2ull * P_ * HP_ * HP_];      // 1.6 MB
__device__ float g_sB[P_ * HP_];
__device__ __align__(16) __half g_Yh[(size_t)B_ * P_ * N_ * HP_]; // 84 MB (fp16 Y)
__device__ float g_logits[B_ * N_];

#define LIMBW ((size_t)P_ * HP_ * HP_)

// ---------------- helpers ----------------
__device__ __forceinline__ float warp_sum(float v) {
#pragma unroll
    for (int o = 16; o; o >>= 1) v += __shfl_xor_sync(0xffffffffu, v, o);
    return v;
}
__device__ __forceinline__ float warp_max(float v) {
#pragma unroll
    for (int o = 16; o; o >>= 1) v = fmaxf(v, __shfl_xor_sync(0xffffffffu, v, o));
    return v;
}
__device__ __forceinline__ uint32_t smem_u32(const void* p) {
    uint32_t a;
    asm("{ .reg .u64 t; cvta.to.shared.u64 t, %1; cvt.u32.u64 %0, t; }" : "=r"(a) : "l"(p));
    return a;
}
__device__ __forceinline__ void cpa16(uint32_t dst, const void* src) {
    asm volatile("cp.async.cg.shared.global [%0], [%1], 16;" :: "r"(dst), "l"(src));
}
#define CPA_COMMIT() asm volatile("cp.async.commit_group;")

__device__ __forceinline__ void ldm4(uint32_t* r, uint32_t a) {
    asm volatile("ldmatrix.sync.aligned.m8n8.x4.shared.b16 {%0,%1,%2,%3}, [%4];"
                 : "=r"(r[0]), "=r"(r[1]), "=r"(r[2]), "=r"(r[3]) : "r"(a));
}
__device__ __forceinline__ void mma_s8(int* c, const uint32_t* a, const uint32_t* b) {
    asm("mma.sync.aligned.m16n8k32.row.col.s32.s8.s8.s32 "
        "{%0,%1,%2,%3},{%4,%5,%6,%7},{%8,%9},{%0,%1,%2,%3};"
        : "+r"(c[0]), "+r"(c[1]), "+r"(c[2]), "+r"(c[3])
        : "r"(a[0]), "r"(a[1]), "r"(a[2]), "r"(a[3]), "r"(b[0]), "r"(b[1]));
}

// ===========================================================================
// K1: quantize W^T: per (p,ko) row over h, 14-bit 2-limb int8 + f32 scale
// ===========================================================================
__global__ void prep_w(const float* __restrict__ W) {
    int t = blockIdx.x * blockDim.x + threadIdx.x;
    if (t >= P_ * HP_) return;
    int p = t / HP_, ko = t % HP_;
    float amax = 0.f;
    if (ko < H_)
        for (int h = 0; h < H_; h++)
            amax = fmaxf(amax, fabsf(W[((size_t)p * H_ + h) * H_ + ko]));
    float inv = amax > 0.f ? QMAXF / amax : 0.f;
    g_sB[t] = amax > 0.f ? amax / QMAXF : 1.f;
    size_t base = (size_t)t * HP_;
    for (int h4 = 0; h4 < HP_ / 4; h4++) {
        uint32_t hw = 0, lw = 0;
#pragma unroll
        for (int e = 0; e < 4; e++) {
            int h = h4 * 4 + e;
            float w = (ko < H_ && h < H_) ? W[((size_t)p * H_ + h) * H_ + ko] : 0.f;
            int q = __float2int_rn(w * inv);
            int hi = (q + 64) >> 7;
            int lo = q - (hi << 7);
            hw |= ((uint32_t)(uint8_t)(int8_t)hi) << (8 * e);
            lw |= ((uint32_t)(uint8_t)(int8_t)lo) << (8 * e);
        }
        *(uint32_t*)(g_Wq + base + h4 * 4) = hw;
        *(uint32_t*)(g_Wq + LIMBW + base + h4 * 4) = lw;
    }
}

// ===========================================================================
// K2: A-RESIDENT int8 2-limb GEMM with IN-KERNEL A quantization.
// grid (N/MT, B*P) = (8, 128) = 1024 blocks; 256 thr = 8 warps (4m x 2n).
// Prologue: warp-per-row fp32 load of node_attr, fold instr, quantize to
// 2-limb int8 directly into smem; per-row scales to smem. Then 5 col tiles
// (4x NF=4 + 1x NF=3), B double-buffered. Y stored fp16.
// ===========================================================================
#define ARSTR 336
#define A_LIMB (128 * ARSTR)        // 43008
#define OFFB  (2 * A_LIMB)          // 86016
#define BRSTR 80
#define BLIMB (64 * BRSTR)          // 5120
#define BSTG  (2 * BLIMB)           // 10240 per stage
#define OFFI  (OFFB + 2 * BSTG)     // 106496  (instr: 320 f32)
#define OFFS  (OFFI + HP_ * 4)      // 107776  (row scales: 128 f32)
#define SMEM_TOT (OFFS + 512)       // 108288  (2 CTAs/SM)

__device__ __forceinline__ void issueB(uint32_t sbase, int p, int nt, int kt, int s,
                                       int brow, int bseg) {
    const uint32_t st = sbase + OFFB + s * BSTG;
    const uint32_t so = (uint32_t)(brow * BRSTR + bseg * 16);
    size_t gb = ((size_t)(p * HP_ + nt * 64 + brow)) * HP_ + kt * KB + bseg * 16;
    cpa16(st + so, g_Wq + gb);
    cpa16(st + BLIMB + so, g_Wq + LIMBW + gb);
}

template <int NF>
__device__ __forceinline__ void do_tile(
    uint32_t sbase, int nt, int p, int m_w, int wn,
    uint32_t aoff, uint32_t boff, int brow, int bseg,
    int g, int tq, const float sa[2][2], int m0, __half* yb, bool preissued)
{
    const int n_w = wn * (NF * 8);
    const int n0  = nt * 64;

    if (!preissued) {
        issueB(sbase, p, nt, 0, 0, brow, bseg); CPA_COMMIT();
        issueB(sbase, p, nt, 1, 1, brow, bseg); CPA_COMMIT();
    }

    int chh[2][NF][4], cmd[2][NF][4];
#pragma unroll
    for (int mf = 0; mf < 2; mf++)
#pragma unroll
        for (int nf = 0; nf < NF; nf++)
#pragma unroll
            for (int e = 0; e < 4; e++) { chh[mf][nf][e] = 0; cmd[mf][nf][e] = 0; }

#pragma unroll 1
    for (int kt = 0; kt < NKT; kt++) {
        if (kt < NKT - 1) { asm volatile("cp.async.wait_group 1;"); }
        else              { asm volatile("cp.async.wait_group 0;"); }
        __syncthreads();

        const uint32_t stg = sbase + OFFB + (uint32_t)((kt & 1) * BSTG);
#pragma unroll
        for (int ks = 0; ks < 2; ks++) {
            const uint32_t kkb = (uint32_t)(ks * 32);
            uint32_t ah[2][4], al[2][4], bh[2][4], blr[2][4];
#pragma unroll
            for (int mf = 0; mf < 2; mf++) {
                uint32_t ba = sbase + (uint32_t)((m_w + mf * 16) * ARSTR)
                              + (uint32_t)(kt * KB) + kkb + aoff;
                ldm4(ah[mf], ba);
                ldm4(al[mf], ba + A_LIMB);
            }
#pragma unroll
            for (int nfp = 0; nfp < 2; nfp++) {
                uint32_t bb = stg + (uint32_t)((n_w + nfp * 16) * BRSTR) + kkb + boff;
                ldm4(bh[nfp], bb);
                ldm4(blr[nfp], bb + BLIMB);
            }
#pragma unroll
            for (int mf = 0; mf < 2; mf++)
#pragma unroll
                for (int nf = 0; nf < NF; nf++) {
                    const uint32_t* ph = &bh[nf >> 1][(nf & 1) * 2];
                    const uint32_t* pl = &blr[nf >> 1][(nf & 1) * 2];
                    mma_s8(chh[mf][nf], ah[mf], ph);   // hi*hi (<<14)
                    mma_s8(cmd[mf][nf], ah[mf], pl);   // hi*lo (<<7)
                    mma_s8(cmd[mf][nf], al[mf], ph);   // lo*hi (<<7)
                }
        }
        __syncthreads();
        if (kt + 2 < NKT) {
            issueB(sbase, p, nt, kt + 2, kt & 1, brow, bseg);
            CPA_COMMIT();
        }
    }

    // ---- apply scales, store Y tile (fp16) ----
#pragma unroll
    for (int mf = 0; mf < 2; mf++)
#pragma unroll
        for (int nf = 0; nf < NF; nf++) {
            int gr = m0 + m_w + mf * 16 + g;
            int gc = n0 + n_w + nf * 8 + 2 * tq;
            float2 sb2 = *(const float2*)(g_sB + p * HP_ + gc);
            float v0 = (float)chh[mf][nf][0] * 16384.f + (float)cmd[mf][nf][0] * 128.f;
            float v1 = (float)chh[mf][nf][1] * 16384.f + (float)cmd[mf][nf][1] * 128.f;
            float v2 = (float)chh[mf][nf][2] * 16384.f + (float)cmd[mf][nf][2] * 128.f;
            float v3 = (float)chh[mf][nf][3] * 16384.f + (float)cmd[mf][nf][3] * 128.f;
            *(__half2*)(yb + (size_t)gr * HP_ + gc) =
                __floats2half2_rn(sa[mf][0] * sb2.x * v0, sa[mf][0] * sb2.y * v1);
            *(__half2*)(yb + (size_t)(gr + 8) * HP_ + gc) =
                __floats2half2_rn(sa[mf][1] * sb2.x * v2, sa[mf][1] * sb2.y * v3);
        }
    __syncthreads();   // stages free before next tile's prologue reuses them
}

__global__ __launch_bounds__(256, 2)
void gemm(const float* __restrict__ na, const float* __restrict__ instr) {
    extern __shared__ char smraw[];
    const uint32_t sbase = smem_u32(smraw);

    const int t = threadIdx.x, lane = t & 31, wid = t >> 5;
    const int g = lane >> 2, tq = lane & 3;
    const int bp = blockIdx.y, b = bp >> 3, p = bp & 7;
    const int m0 = blockIdx.x * MT;
    const int wm = wid & 3, wn = wid >> 2;
    const int m_w = wm * 32;

    const int brow = t >> 2, bseg = t & 3;
    const uint32_t aoff = (uint32_t)((lane & 15) * ARSTR + ((lane >> 4) << 4));
    const uint32_t boff = (uint32_t)((((lane & 7) + ((lane >> 4) << 3)) * BRSTR) +
                                     (((lane >> 3) & 1) << 4));

    float* sI = (float*)(smraw + OFFI);
    float* sS = (float*)(smraw + OFFS);

    // pre-issue tile0's B stages so they fly during A conversion
    issueB(sbase, p, 0, 0, 0, brow, bseg); CPA_COMMIT();
    issueB(sbase, p, 0, 1, 1, brow, bseg); CPA_COMMIT();

    // instruction row to smem
    for (int i = t; i < HP_; i += 256) sI[i] = (i < H_) ? instr[b * H_ + i] : 0.f;
    __syncthreads();

    // ---- in-kernel A quantization: warp-per-row, 16 rows per warp ----
    int8_t* Ah8 = (int8_t*)smraw;
    int8_t* Al8 = (int8_t*)smraw + A_LIMB;
#pragma unroll 1
    for (int r = wid; r < MT; r += 8) {
        const float* src = na + ((size_t)((b * N_ + m0 + r) * P_) + p) * H_;
        float4 v[3];
        float amax = 0.f;
#pragma unroll
        for (int j = 0; j < 3; j++) {
            int k = 4 * (lane + 32 * j);
            float4 x = make_float4(0.f, 0.f, 0.f, 0.f);
            if (k < H_) {                  // H_ % 4 == 0: float4 never straddles
                x = *(const float4*)(src + k);
                float4 iv = *(const float4*)(sI + k);
                x.x *= iv.x; x.y *= iv.y; x.z *= iv.z; x.w *= iv.w;
            }
            v[j] = x;
            amax = fmaxf(amax, fmaxf(fmaxf(fabsf(x.x), fabsf(x.y)),
                                     fmaxf(fabsf(x.z), fabsf(x.w))));
        }
        amax = warp_max(amax);
        float inv = amax > 0.f ? QMAXF / amax : 0.f;
        if (lane == 0) sS[r] = amax > 0.f ? amax / QMAXF : 1.f;
#pragma unroll
        for (int j = 0; j < 3; j++) {
            int w = lane + 32 * j;
            if (w < HP_ / 4) {
                uint32_t hw = 0, lw = 0;
                const float* xe = (const float*)&v[j];
#pragma unroll
                for (int e = 0; e < 4; e++) {
                    int q = __float2int_rn(xe[e] * inv);
                    int hi = (q + 64) >> 7;
                    int lo = q - (hi << 7);
                    hw |= ((uint32_t)(uint8_t)(int8_t)hi) << (8 * e);
                    lw |= ((uint32_t)(uint8_t)(int8_t)lo) << (8 * e);
                }
                *(uint32_t*)(Ah8 + r * ARSTR + 4 * w) = hw;
                *(uint32_t*)(Al8 + r * ARSTR + 4 * w) = lw;
            }
        }
    }
    __syncthreads();

    float sa[2][2];
#pragma unroll
    for (int mf = 0; mf < 2; mf++)
#pragma unroll
        for (int hh = 0; hh < 2; hh++)
            sa[mf][hh] = sS[m_w + mf * 16 + g + hh * 8];

    __half* yb = g_Yh + (size_t)(b * P_ + p) * N_ * HP_;

    do_tile<4>(sbase, 0, p, m_w, wn, aoff, boff, brow, bseg, g, tq, sa, m0, yb, true);
#pragma unroll 1
    for (int nt = 1; nt < 4; nt++)
        do_tile<4>(sbase, nt, p, m_w, wn, aoff, boff, brow, bseg, g, tq, sa, m0, yb, false);
    do_tile<3>(sbase, 4, p, m_w, wn, aoff, boff, brow, bseg, g, tq, sa, m0, yb, false);
}

// ===========================================================================
// K3: per-(b,n) row, one warp each; 4-half vector loads of fp16 Y
// ===========================================================================
__global__ __launch_bounds__(256)
void epilogue(const float* __restrict__ sim,
              const float* __restrict__ wss,
              const float* __restrict__ mask) {
    const int gw = (blockIdx.x * blockDim.x + threadIdx.x) >> 5;  // b*N + n
    const int lane = threadIdx.x & 31;
    const int b = gw >> 10, n = gw & 1023;
    const __half* base = g_Yh + ((size_t)b * P_ * N_ + n) * HP_;

    float sp[P_];
#pragma unroll
    for (int p = 0; p < P_; p++) sp[p] = sim[b * P_ + p];

    float acc = 0.f;
#pragma unroll
    for (int j = 0; j < 3; j++) {
        int w = lane + 32 * j;          // 4-half word; k = 4w
        if (w < H_ / 4) {
            float4 s4 = make_float4(0.f, 0.f, 0.f, 0.f);
            float4 q4 = make_float4(0.f, 0.f, 0.f, 0.f);
#pragma unroll
            for (int p = 0; p < P_; p++) {
                uint2 u = *(const uint2*)(base + (size_t)p * (N_ * HP_) + 4 * w);
                float2 f01 = __half22float2(*(__half2*)&u.x);
                float2 f23 = __half22float2(*(__half2*)&u.y);
                float vx = sp[p] * f01.x, vy = sp[p] * f01.y;
                float vz = sp[p] * f23.x, vw = sp[p] * f23.y;
                s4.x += vx; s4.y += vy; s4.z += vz; s4.w += vw;
                q4.x = fmaf(vx, vx, q4.x); q4.y = fmaf(vy, vy, q4.y);
                q4.z = fmaf(vz, vz, q4.z); q4.w = fmaf(vw, vw, q4.w);
            }
            float4 wv = *(const float4*)(wss + 4 * w);
            float sc, el;
            sc = s4.x / fmaxf(sqrtf(q4.x), 1e-12f);
            el = sc > 0.f ? sc : expm1f(sc);  acc += el * wv.x;
            sc = s4.y / fmaxf(sqrtf(q4.y), 1e-12f);
            el = sc > 0.f ? sc : expm1f(sc);  acc += el * wv.y;
            sc = s4.z / fmaxf(sqrtf(q4.z), 1e-12f);
            el = sc > 0.f ? sc : expm1f(sc);  acc += el * wv.z;
            sc = s4.w / fmaxf(sqrtf(q4.w), 1e-12f);
            el = sc > 0.f ? sc : expm1f(sc);  acc += el * wv.w;
        }
    }
    acc = warp_sum(acc);
    if (lane == 0) g_logits[gw] = acc + mask[gw];
}

// ===========================================================================
// K4: softmax over N per batch
// ===========================================================================
__global__ __launch_bounds__(1024)
void softmax_kernel(float* __restrict__ out) {
    const int b = blockIdx.x, t = threadIdx.x;
    float v = g_logits[b * N_ + t];
    __shared__ float red[32];
    const int lane = t & 31, wid = t >> 5;

    float m = warp_max(v);
    if (lane == 0) red[wid] = m;
    __syncthreads();
    if (wid == 0) red[lane] = warp_max(red[lane]);
    __syncthreads();
    m = red[0];
    __syncthreads();

    float e = expf(v - m);
    float s = warp_sum(e);
    if (lane == 0) red[wid] = s;
    __syncthreads();
    if (wid == 0) red[lane] = warp_sum(red[lane]);
    __syncthreads();
    s = red[0];

    out[b * N_ + t] = e / s;
}

// ===========================================================================
extern "C" void kernel_launch(void* const* d_in, const int* in_sizes, int n_in,
                              void* d_out, int out_size) {
    const float* node_attr = (const float*)d_in[0];
    const float* instr     = (const float*)d_in[2];
    const float* sim       = (const float*)d_in[4];
    const float* mask      = (const float*)d_in[5];
    const float* W         = (const float*)d_in[6];
    const float* wss       = (const float*)d_in[7];
    float* out = (float*)d_out;

    cudaFuncSetAttribute(gemm, cudaFuncAttributeMaxDynamicSharedMemorySize, SMEM_TOT);

    prep_w<<<(P_ * HP_ + 255) / 256, 256>>>(W);

    dim3 gg(N_ / MT, B_ * P_);   // (8, 128) = 1024 blocks
    gemm<<<gg, 256, SMEM_TOT>>>(node_attr, instr);

    epilogue<<<(B_ * N_) / 8, 256>>>(sim, wss, mask);

    softmax_kernel<<<B_, 1024>>>(out);
}

// round 16
// speedup vs baseline: 1.1053x; 1.1053x over previous
#include <cuda_runtime.h>
#include <cuda_fp16.h>
#include <cstdint>
#include <math.h>

#define B_   16
#define N_   1024
#define P_   8
#define H_   300
#define HP_  320
#define MT   128
#define KB   64      // int8 k-elems per chunk (2 mma k-steps)
#define NKT  5       // 320/64

#define QMAXF 16256.0f   // 127*128

// ---------------- device-global scratch ----------------
__device__ __align__(16) int8_t g_Aq[2ull * B_ * N_ * P_ * HP_];  // 84 MB (hi|lo)
__device__ __align__(16) int8_t g_Wq[2ull * P_ * HP_ * HP_];      // 1.6 MB
__device__ float g_sA[B_ * N_ * P_];
__device__ float g_sB[P_ * HP_];
__device__ __align__(16) __half g_Yh[(size_t)B_ * P_ * N_ * HP_]; // 84 MB (fp16 Y)
__device__ float g_logits[B_ * N_];

#define LIMBA ((size_t)B_ * N_ * P_ * HP_)
#define LIMBW ((size_t)P_ * HP_ * HP_)

// ---------------- helpers ----------------
__device__ __forceinline__ float warp_sum(float v) {
#pragma unroll
    for (int o = 16; o; o >>= 1) v += __shfl_xor_sync(0xffffffffu, v, o);
    return v;
}
__device__ __forceinline__ float warp_max(float v) {
#pragma unroll
    for (int o = 16; o; o >>= 1) v = fmaxf(v, __shfl_xor_sync(0xffffffffu, v, o));
    return v;
}
__device__ __forceinline__ uint32_t smem_u32(const void* p) {
    uint32_t a;
    asm("{ .reg .u64 t; cvta.to.shared.u64 t, %1; cvt.u32.u64 %0, t; }" : "=r"(a) : "l"(p));
    return a;
}
__device__ __forceinline__ void cpa16(uint32_t dst, const void* src) {
    asm volatile("cp.async.cg.shared.global [%0], [%1], 16;" :: "r"(dst), "l"(src));
}
#define CPA_COMMIT() asm volatile("cp.async.commit_group;")

__device__ __forceinline__ void ldm4(uint32_t* r, uint32_t a) {
    asm volatile("ldmatrix.sync.aligned.m8n8.x4.shared.b16 {%0,%1,%2,%3}, [%4];"
                 : "=r"(r[0]), "=r"(r[1]), "=r"(r[2]), "=r"(r[3]) : "r"(a));
}
__device__ __forceinline__ void mma_s8(int* c, const uint32_t* a, const uint32_t* b) {
    asm("mma.sync.aligned.m16n8k32.row.col.s32.s8.s8.s32 "
        "{%0,%1,%2,%3},{%4,%5,%6,%7},{%8,%9},{%0,%1,%2,%3};"
        : "+r"(c[0]), "+r"(c[1]), "+r"(c[2]), "+r"(c[3])
        : "r"(a[0]), "r"(a[1]), "r"(a[2]), "r"(a[3]), "r"(b[0]), "r"(b[1]));
}

// ===========================================================================
// K1: quantize W^T; 4 lanes per (p,ko) group (h split in 80-wide ranges)
// ===========================================================================
__global__ __launch_bounds__(256)
void prep_w(const float* __restrict__ W) {
    int gid = blockIdx.x * blockDim.x + threadIdx.x;
    int grp = gid >> 2, sub = gid & 3;
    if (grp >= P_ * HP_) return;
    int p = grp / HP_, ko = grp % HP_;

    const int h0 = sub * 80, h1 = h0 + 80;
    float amax = 0.f;
    if (ko < H_) {
        for (int h = h0; h < h1 && h < H_; h++)
            amax = fmaxf(amax, fabsf(W[((size_t)p * H_ + h) * H_ + ko]));
    }
    // combine across the 4 subs (4-aligned lanes within one warp)
    amax = fmaxf(amax, __shfl_xor_sync(0xffffffffu, amax, 1));
    amax = fmaxf(amax, __shfl_xor_sync(0xffffffffu, amax, 2));

    float inv = amax > 0.f ? QMAXF / amax : 0.f;
    if (sub == 0) g_sB[grp] = amax > 0.f ? amax / QMAXF : 1.f;

    size_t base = (size_t)grp * HP_;
    for (int w = h0 / 4; w < h1 / 4; w++) {
        uint32_t hw = 0, lw = 0;
#pragma unroll
        for (int e = 0; e < 4; e++) {
            int h = w * 4 + e;
            float wv = (ko < H_ && h < H_) ? W[((size_t)p * H_ + h) * H_ + ko] : 0.f;
            int q = __float2int_rn(wv * inv);
            int hi = (q + 64) >> 7;
            int lo = q - (hi << 7);
            hw |= ((uint32_t)(uint8_t)(int8_t)hi) << (8 * e);
            lw |= ((uint32_t)(uint8_t)(int8_t)lo) << (8 * e);
        }
        *(uint32_t*)(g_Wq + base + w * 4) = hw;
        *(uint32_t*)(g_Wq + LIMBW + base + w * 4) = lw;
    }
}

// ===========================================================================
// K2: quantize A: one warp per (b,n,p) row; vectorized word stores
// ===========================================================================
__global__ __launch_bounds__(256)
void prep_a(const float* __restrict__ na, const float* __restrict__ instr) {
    int gw = (blockIdx.x * blockDim.x + threadIdx.x) >> 5;
    int lane = threadIdx.x & 31;
    if (gw >= B_ * N_ * P_) return;
    int b = gw >> 13;
    const float* src = na + (size_t)gw * H_;
    const float* ib  = instr + b * H_;

    float4 v[3];
    float amax = 0.f;
#pragma unroll
    for (int j = 0; j < 3; j++) {
        int w = j * 32 + lane;
        int k = w * 4;
        float4 x = make_float4(0.f, 0.f, 0.f, 0.f);
        if (k < H_) {
            x = *(const float4*)(src + k);
            x.x *= ib[k]; x.y *= ib[k + 1]; x.z *= ib[k + 2]; x.w *= ib[k + 3];
        }
        v[j] = x;
        amax = fmaxf(amax, fmaxf(fmaxf(fabsf(x.x), fabsf(x.y)),
                                 fmaxf(fabsf(x.z), fabsf(x.w))));
    }
    amax = warp_max(amax);
    float inv = amax > 0.f ? QMAXF / amax : 0.f;
    if (lane == 0) g_sA[gw] = amax > 0.f ? amax / QMAXF : 1.f;

    size_t base = (size_t)gw * HP_;
#pragma unroll
    for (int j = 0; j < 3; j++) {
        int w = j * 32 + lane;
        if (w < HP_ / 4) {
            uint32_t hw = 0, lw = 0;
            const float* xe = (const float*)&v[j];
#pragma unroll
            for (int e = 0; e < 4; e++) {
                int q = __float2int_rn(xe[e] * inv);
                int hi = (q + 64) >> 7;
                int lo = q - (hi << 7);
                hw |= ((uint32_t)(uint8_t)(int8_t)hi) << (8 * e);
                lw |= ((uint32_t)(uint8_t)(int8_t)lo) << (8 * e);
            }
            *(uint32_t*)(g_Aq + base + w * 4) = hw;
            *(uint32_t*)(g_Aq + LIMBA + base + w * 4) = lw;
        }
    }
}

// ===========================================================================
// K3: A-RESIDENT int8 2-limb GEMM. grid (N/MT, B*P) = (8, 128) = 1024 blocks.
// A slice loaded once; 5 col tiles (4x NF=4 + 1x NF=3), B double-buffered.
// Y stored fp16 with sim_p FOLDED into the row scale.
// ===========================================================================
#define ARSTR 336
#define A_LIMB (128 * ARSTR)        // 43008
#define OFFB  (2 * A_LIMB)          // 86016
#define BRSTR 80
#define BLIMB (64 * BRSTR)          // 5120
#define BSTG  (2 * BLIMB)           // 10240 per stage
#define SMEM_TOT (OFFB + 2 * BSTG)  // 106496

__device__ __forceinline__ void issueB(uint32_t sbase, int p, int nt, int kt, int s,
                                       int brow, int bseg) {
    const uint32_t st = sbase + OFFB + s * BSTG;
    const uint32_t so = (uint32_t)(brow * BRSTR + bseg * 16);
    size_t gb = ((size_t)(p * HP_ + nt * 64 + brow)) * HP_ + kt * KB + bseg * 16;
    cpa16(st + so, g_Wq + gb);
    cpa16(st + BLIMB + so, g_Wq + LIMBW + gb);
}

template <int NF>
__device__ __forceinline__ void do_tile(
    uint32_t sbase, int nt, int p, int m_w, int wn,
    uint32_t aoff, uint32_t boff, int brow, int bseg,
    int g, int tq, const float sa[2][2], int m0, __half* yb)
{
    const int n_w = wn * (NF * 8);
    const int n0  = nt * 64;

    issueB(sbase, p, nt, 0, 0, brow, bseg); CPA_COMMIT();
    issueB(sbase, p, nt, 1, 1, brow, bseg); CPA_COMMIT();

    int chh[2][NF][4], cmd[2][NF][4];
#pragma unroll
    for (int mf = 0; mf < 2; mf++)
#pragma unroll
        for (int nf = 0; nf < NF; nf++)
#pragma unroll
            for (int e = 0; e < 4; e++) { chh[mf][nf][e] = 0; cmd[mf][nf][e] = 0; }

#pragma unroll 1
    for (int kt = 0; kt < NKT; kt++) {
        if (kt < NKT - 1) { asm volatile("cp.async.wait_group 1;"); }
        else              { asm volatile("cp.async.wait_group 0;"); }
        __syncthreads();

        const uint32_t stg = sbase + OFFB + (uint32_t)((kt & 1) * BSTG);
#pragma unroll
        for (int ks = 0; ks < 2; ks++) {
            const uint32_t kkb = (uint32_t)(ks * 32);
            uint32_t ah[2][4], al[2][4], bh[2][4], blr[2][4];
#pragma unroll
            for (int mf = 0; mf < 2; mf++) {
                uint32_t ba = sbase + (uint32_t)((m_w + mf * 16) * ARSTR)
                              + (uint32_t)(kt * KB) + kkb + aoff;
                ldm4(ah[mf], ba);
                ldm4(al[mf], ba + A_LIMB);
            }
#pragma unroll
            for (int nfp = 0; nfp < 2; nfp++) {
                uint32_t bb = stg + (uint32_t)((n_w + nfp * 16) * BRSTR) + kkb + boff;
                ldm4(bh[nfp], bb);
                ldm4(blr[nfp], bb + BLIMB);
            }
#pragma unroll
            for (int mf = 0; mf < 2; mf++)
#pragma unroll
                for (int nf = 0; nf < NF; nf++) {
                    const uint32_t* ph = &bh[nf >> 1][(nf & 1) * 2];
                    const uint32_t* pl = &blr[nf >> 1][(nf & 1) * 2];
                    mma_s8(chh[mf][nf], ah[mf], ph);   // hi*hi (<<14)
                    mma_s8(cmd[mf][nf], ah[mf], pl);   // hi*lo (<<7)
                    mma_s8(cmd[mf][nf], al[mf], ph);   // lo*hi (<<7)
                }
        }
        __syncthreads();
        if (kt + 2 < NKT) {
            issueB(sbase, p, nt, kt + 2, kt & 1, brow, bseg);
            CPA_COMMIT();
        }
    }

    // ---- apply scales (incl. sim_p), store Y tile (fp16) ----
#pragma unroll
    for (int mf = 0; mf < 2; mf++)
#pragma unroll
        for (int nf = 0; nf < NF; nf++) {
            int gr = m0 + m_w + mf * 16 + g;
            int gc = n0 + n_w + nf * 8 + 2 * tq;
            float2 sb2 = *(const float2*)(g_sB + p * HP_ + gc);
            float v0 = (float)chh[mf][nf][0] * 16384.f + (float)cmd[mf][nf][0] * 128.f;
            float v1 = (float)chh[mf][nf][1] * 16384.f + (float)cmd[mf][nf][1] * 128.f;
            float v2 = (float)chh[mf][nf][2] * 16384.f + (float)cmd[mf][nf][2] * 128.f;
            float v3 = (float)chh[mf][nf][3] * 16384.f + (float)cmd[mf][nf][3] * 128.f;
            *(__half2*)(yb + (size_t)gr * HP_ + gc) =
                __floats2half2_rn(sa[mf][0] * sb2.x * v0, sa[mf][0] * sb2.y * v1);
            *(__half2*)(yb + (size_t)(gr + 8) * HP_ + gc) =
                __floats2half2_rn(sa[mf][1] * sb2.x * v2, sa[mf][1] * sb2.y * v3);
        }
    __syncthreads();   // stages free before next tile's prologue reuses them
}

__global__ __launch_bounds__(256, 2)
void gemm(const float* __restrict__ sim) {
    extern __shared__ char smraw[];
    const uint32_t sbase = smem_u32(smraw);

    const int t = threadIdx.x, lane = t & 31, wid = t >> 5;
    const int g = lane >> 2, tq = lane & 3;
    const int bp = blockIdx.y, b = bp >> 3, p = bp & 7;
    const int m0 = blockIdx.x * MT;
    const int wm = wid & 3, wn = wid >> 2;
    const int m_w = wm * 32;

    const int brow = t >> 2, bseg = t & 3;
    const uint32_t aoff = (uint32_t)((lane & 15) * ARSTR + ((lane >> 4) << 4));
    const uint32_t boff = (uint32_t)((((lane & 7) + ((lane >> 4) << 3)) * BRSTR) +
                                     (((lane >> 3) & 1) << 4));

    // ---- A resident: 128 rows x 20 segs x 2 limbs ----
#pragma unroll
    for (int limb = 0; limb < 2; limb++) {
        const int8_t* ga = g_Aq + (size_t)limb * LIMBA;
        const uint32_t sa0 = sbase + limb * A_LIMB;
#pragma unroll
        for (int i = 0; i < 10; i++) {
            int u = t + i * 256;               // 0..2559
            int row = u / 20, seg = u % 20;
            cpa16(sa0 + row * ARSTR + seg * 16,
                  ga + ((size_t)((b * N_ + m0 + row) * P_) + p) * HP_ + seg * 16);
        }
    }

    const float simv = __ldg(&sim[b * P_ + p]);
    float sa[2][2];
#pragma unroll
    for (int mf = 0; mf < 2; mf++)
#pragma unroll
        for (int hh = 0; hh < 2; hh++) {
            int row = m0 + m_w + mf * 16 + g + hh * 8;
            sa[mf][hh] = simv * g_sA[(b * N_ + row) * P_ + p];
        }

    __half* yb = g_Yh + (size_t)(b * P_ + p) * N_ * HP_;

#pragma unroll 1
    for (int nt = 0; nt < 4; nt++)
        do_tile<4>(sbase, nt, p, m_w, wn, aoff, boff, brow, bseg, g, tq, sa, m0, yb);
    do_tile<3>(sbase, 4, p, m_w, wn, aoff, boff, brow, bseg, g, tq, sa, m0, yb);
}

// ===========================================================================
// K4: per-(b,n) row, one warp each; Y already carries sim_p
// ===========================================================================
__global__ __launch_bounds__(256)
void epilogue(const float* __restrict__ wss,
              const float* __restrict__ mask) {
    const int gw = (blockIdx.x * blockDim.x + threadIdx.x) >> 5;  // b*N + n
    const int lane = threadIdx.x & 31;
    const int b = gw >> 10, n = gw & 1023;
    const __half* base = g_Yh + ((size_t)b * P_ * N_ + n) * HP_;

    float acc = 0.f;
#pragma unroll
    for (int j = 0; j < 3; j++) {
        int w = lane + 32 * j;          // 4-half word; k = 4w
        if (w < H_ / 4) {
            float4 s4 = make_float4(0.f, 0.f, 0.f, 0.f);
            float4 q4 = make_float4(0.f, 0.f, 0.f, 0.f);
#pragma unroll
            for (int p = 0; p < P_; p++) {
                uint2 u = *(const uint2*)(base + (size_t)p * (N_ * HP_) + 4 * w);
                float2 f01 = __half22float2(*(__half2*)&u.x);
                float2 f23 = __half22float2(*(__half2*)&u.y);
                s4.x += f01.x; s4.y += f01.y; s4.z += f23.x; s4.w += f23.y;
                q4.x = fmaf(f01.x, f01.x, q4.x); q4.y = fmaf(f01.y, f01.y, q4.y);
                q4.z = fmaf(f23.x, f23.x, q4.z); q4.w = fmaf(f23.y, f23.y, q4.w);
            }
            float4 wv = *(const float4*)(wss + 4 * w);
            float sc, el;
            sc = s4.x / fmaxf(sqrtf(q4.x), 1e-12f);
            el = sc > 0.f ? sc : expm1f(sc);  acc += el * wv.x;
            sc = s4.y / fmaxf(sqrtf(q4.y), 1e-12f);
            el = sc > 0.f ? sc : expm1f(sc);  acc += el * wv.y;
            sc = s4.z / fmaxf(sqrtf(q4.z), 1e-12f);
            el = sc > 0.f ? sc : expm1f(sc);  acc += el * wv.z;
            sc = s4.w / fmaxf(sqrtf(q4.w), 1e-12f);
            el = sc > 0.f ? sc : expm1f(sc);  acc += el * wv.w;
        }
    }
    acc = warp_sum(acc);
    if (lane == 0) g_logits[gw] = acc + mask[gw];
}

// ===========================================================================
// K5: softmax over N per batch
// ===========================================================================
__global__ __launch_bounds__(1024)
void softmax_kernel(float* __restrict__ out) {
    const int b = blockIdx.x, t = threadIdx.x;
    float v = g_logits[b * N_ + t];
    __shared__ float red[32];
    const int lane = t & 31, wid = t >> 5;

    float m = warp_max(v);
    if (lane == 0) red[wid] = m;
    __syncthreads();
    if (wid == 0) red[lane] = warp_max(red[lane]);
    __syncthreads();
    m = red[0];
    __syncthreads();

    float e = expf(v - m);
    float s = warp_sum(e);
    if (lane == 0) red[wid] = s;
    __syncthreads();
    if (wid == 0) red[lane] = warp_sum(red[lane]);
    __syncthreads();
    s = red[0];

    out[b * N_ + t] = e / s;
}

// ===========================================================================
extern "C" void kernel_launch(void* const* d_in, const int* in_sizes, int n_in,
                              void* d_out, int out_size) {
    const float* node_attr = (const float*)d_in[0];
    const float* instr     = (const float*)d_in[2];
    const float* sim       = (const float*)d_in[4];
    const float* mask      = (const float*)d_in[5];
    const float* W         = (const float*)d_in[6];
    const float* wss       = (const float*)d_in[7];
    float* out = (float*)d_out;

    cudaFuncSetAttribute(gemm, cudaFuncAttributeMaxDynamicSharedMemorySize, SMEM_TOT);

    prep_w<<<(P_ * HP_ * 4 + 255) / 256, 256>>>(W);

    const int nwarps = B_ * N_ * P_;
    prep_a<<<nwarps / 8, 256>>>(node_attr, instr);

    dim3 gg(N_ / MT, B_ * P_);   // (8, 128) = 1024 blocks
    gemm<<<gg, 256, SMEM_TOT>>>(sim);

    epilogue<<<(B_ * N_) / 8, 256>>>(wss, mask);

    softmax_kernel<<<B_, 1024>>>(out);
}